// round 1
// baseline (speedup 1.0000x reference)
#include <cuda_runtime.h>
#include <cuda_bf16.h>
#include <math.h>

// Problem shape (fixed by the dataset)
#define BB 16
#define NN 1024
#define VV 4096
#define TT 8
#define NG (BB*TT)       // 128 (batch, type) groups
#define KMAX 160         // max group size (mean 64, sd ~7.8 -> 12 sigma headroom)
#define CPL 5            // columns per lane = KMAX/32

// ---------------- device scratch (static; no allocations) ----------------
__device__ int    d_mask_code;          // 0=uint8, 1=int32, 2=float32
__device__ int    d_cnt[NG];
__device__ int    d_idx[NG][KMAX];
__device__ int    d_tok[NG][KMAX];
__device__ float  d_cost[NG][KMAX*KMAX];
__device__ float  d_lse[BB*NN];
__device__ double d_val[NG];

// ---------------- helpers ----------------
__device__ __forceinline__ bool mask_at(const void* m, int code, int i) {
    if (code == 0) return ((const unsigned char*)m)[i] != 0;
    if (code == 1) return ((const int*)m)[i] != 0;
    return ((const float*)m)[i] != 0.0f;
}

// order-preserving float -> uint key (monotone), and inverse
__device__ __forceinline__ unsigned fkey(float f) {
    unsigned b = __float_as_uint(f);
    return (b & 0x80000000u) ? ~b : (b | 0x80000000u);
}
__device__ __forceinline__ float fkey_inv(unsigned k) {
    unsigned b = (k & 0x80000000u) ? (k ^ 0x80000000u) : ~k;
    return __uint_as_float(b);
}

// ---------------- kernel 1: classify mask dtype layout ----------------
__global__ void detect_mask_kernel(const unsigned char* m) {
    __shared__ int nz[4];
    if (threadIdx.x < 4) nz[threadIdx.x] = 0;
    __syncthreads();
    int local[4] = {0,0,0,0};
    for (int i = threadIdx.x; i < BB*NN; i += blockDim.x)
        if (m[i]) local[i & 3] = 1;
    for (int c = 0; c < 4; c++) if (local[c]) atomicOr(&nz[c], 1);
    __syncthreads();
    if (threadIdx.x == 0) {
        int code;
        if (nz[1])      code = 0;  // bytes at offset%4==1 nonzero -> uint8/bool layout
        else if (nz[0]) code = 1;  // only LSB of each word -> int32 0/1
        else            code = 2;  // pattern of 1.0f (bytes 2,3) -> float32
        d_mask_code = code;
    }
}

// ---------------- kernel 2: build (b,type) groups (ordered, deterministic) ---
__global__ void group_build_kernel(const int* __restrict__ gt,
                                   const int* __restrict__ types,
                                   const void* mask) {
    int g = blockIdx.x;
    int b = g / TT, t = g % TT;
    int lane = threadIdx.x;
    int code = d_mask_code;
    int base = b * NN;
    int cnt = 0;
    for (int p0 = 0; p0 < NN; p0 += 32) {
        int pos = p0 + lane;
        bool pred = (types[base + pos] == t) && mask_at(mask, code, base + pos);
        unsigned bal = __ballot_sync(0xFFFFFFFFu, pred);
        if (pred) {
            int r = cnt + __popc(bal & ((1u << lane) - 1u));
            if (r < KMAX) {
                d_idx[g][r] = pos;
                d_tok[g][r] = gt[base + pos];
            }
        }
        cnt += __popc(bal);
    }
    if (lane == 0) d_cnt[g] = min(cnt, KMAX);
}

// ---------------- kernel 3: per-masked-row logsumexp (memory-bound bulk) ----
__global__ void lse_kernel(const float* __restrict__ logits, const void* mask) {
    int r = blockIdx.x;                     // 0 .. BB*NN-1
    if (!mask_at(mask, d_mask_code, r)) {
        if (threadIdx.x == 0) d_lse[r] = 0.0f;
        return;
    }
    const float4* row = (const float4*)(logits + (size_t)r * VV);  // 1024 float4
    int t = threadIdx.x;                    // blockDim = 128
    float4 vb[8];
    float mx = -INFINITY;
    #pragma unroll
    for (int q = 0; q < 8; q++) {
        vb[q] = row[t + q * 128];
        mx = fmaxf(mx, fmaxf(fmaxf(vb[q].x, vb[q].y), fmaxf(vb[q].z, vb[q].w)));
    }
    __shared__ float sm[4];
    #pragma unroll
    for (int o = 16; o > 0; o >>= 1) mx = fmaxf(mx, __shfl_xor_sync(0xFFFFFFFFu, mx, o));
    if ((t & 31) == 0) sm[t >> 5] = mx;
    __syncthreads();
    mx = fmaxf(fmaxf(sm[0], sm[1]), fmaxf(sm[2], sm[3]));
    float s = 0.0f;
    #pragma unroll
    for (int q = 0; q < 8; q++)
        s += __expf(vb[q].x - mx) + __expf(vb[q].y - mx)
           + __expf(vb[q].z - mx) + __expf(vb[q].w - mx);
    __shared__ float ss[4];
    #pragma unroll
    for (int o = 16; o > 0; o >>= 1) s += __shfl_xor_sync(0xFFFFFFFFu, s, o);
    if ((t & 31) == 0) ss[t >> 5] = s;
    __syncthreads();
    if (t == 0) d_lse[r] = mx + logf(ss[0] + ss[1] + ss[2] + ss[3]);
}

// ---------------- kernel 4: gather cost matrices (cost = -logit) ------------
__global__ void gather_kernel(const float* __restrict__ logits) {
    int g = blockIdx.x;
    int k = d_cnt[g];
    if (k == 0) return;
    int b = g / TT;
    const float* base = logits + (size_t)b * NN * VV;
    int kk = k * k;
    for (int e = threadIdx.x; e < kk; e += blockDim.x) {
        int i = e / k, j = e - i * k;
        d_cost[g][i * KMAX + j] = -base[(size_t)d_idx[g][i] * VV + d_tok[g][j]];
    }
}

// ---------------- kernel 5: Jonker-Volgenant LSA, one warp per group --------
// Exact mirror of the reference e-maxx JV; only the optimal VALUE matters
// (unique at the optimum), so lane/column striping is safe.
__global__ void jv_kernel() {
    int g = blockIdx.x;
    int n = d_cnt[g];
    int lane = threadIdx.x;
    __shared__ float u_sh[KMAX + 1];
    __shared__ int   p_sh[KMAX + 1];
    __shared__ int   way_sh[KMAX + 1];
    if (n == 0) { if (lane == 0) d_val[g] = 0.0; return; }
    const float* cost = d_cost[g];

    float v[CPL], minv[CPL];
    #pragma unroll
    for (int q = 0; q < CPL; q++) v[q] = 0.0f;
    for (int q = lane; q <= n; q += 32) { u_sh[q] = 0.0f; p_sh[q] = 0; }
    __syncwarp();

    for (int i = 1; i <= n; i++) {
        if (lane == 0) p_sh[0] = i;
        unsigned usedm = 0;
        #pragma unroll
        for (int q = 0; q < CPL; q++) minv[q] = INFINITY;
        __syncwarp();

        int j0 = 0;
        while (true) {
            // used[j0] = true
            if (j0 > 0) {
                int ol = (j0 - 1) & 31, oq = (j0 - 1) >> 5;
                if (lane == ol) usedm |= (1u << oq);
            }
            int i0 = p_sh[j0];
            float ui0 = u_sh[i0];
            const float* crow = cost + (size_t)(i0 - 1) * KMAX;

            unsigned bestkey = 0xFFFFFFFFu;
            int bestj = 0x7FFFFFFF;
            #pragma unroll
            for (int q = 0; q < CPL; q++) {
                int j = q * 32 + lane + 1;
                if (j <= n && !((usedm >> q) & 1u)) {
                    float cur = crow[j - 1] - ui0 - v[q];
                    if (cur < minv[q]) { minv[q] = cur; way_sh[j] = j0; }
                    unsigned kb = fkey(minv[q]);
                    if (kb < bestkey) { bestkey = kb; bestj = j; }
                }
            }
            unsigned kmin = __reduce_min_sync(0xFFFFFFFFu, bestkey);
            int jc = (bestkey == kmin) ? bestj : 0x7FFFFFFF;
            int j1 = (int)__reduce_min_sync(0xFFFFFFFFu, (unsigned)jc);
            float delta = fkey_inv(kmin);

            // u[p[used]] += delta; v[used] -= delta; minv[~used] -= delta
            if (lane == 0) u_sh[p_sh[0]] += delta;
            #pragma unroll
            for (int q = 0; q < CPL; q++) {
                int j = q * 32 + lane + 1;
                if (j <= n) {
                    if ((usedm >> q) & 1u) { v[q] -= delta; u_sh[p_sh[j]] += delta; }
                    else                   { minv[q] -= delta; }
                }
            }
            __syncwarp();
            j0 = j1;
            if (p_sh[j0] == 0) break;
        }
        // augment along the alternating path
        if (lane == 0) {
            int j = j0;
            while (j) { int jp = way_sh[j]; p_sh[j] = p_sh[jp]; j = jp; }
        }
        __syncwarp();
    }

    // optimal value = sum_j cost[p[j]-1][j-1]
    double s = 0.0;
    for (int j = lane + 1; j <= n; j += 32) {
        int pi = p_sh[j];
        s += (double)cost[(size_t)(pi - 1) * KMAX + (j - 1)];
    }
    #pragma unroll
    for (int o = 16; o > 0; o >>= 1) s += __shfl_down_sync(0xFFFFFFFFu, s, o);
    if (lane == 0) d_val[g] = s;
}

// ---------------- kernel 6: deterministic final reduction -------------------
__global__ void final_kernel(float* out) {
    __shared__ double red[256];
    __shared__ int    redc[256];
    int t = threadIdx.x;
    double s = 0.0;
    for (int i = t; i < BB*NN; i += 256) s += (double)d_lse[i];
    int cnt = 0;
    if (t < NG) { s += d_val[t]; cnt = d_cnt[t]; }
    red[t] = s; redc[t] = cnt;
    __syncthreads();
    for (int o = 128; o > 0; o >>= 1) {
        if (t < o) { red[t] += red[t + o]; redc[t] += redc[t + o]; }
        __syncthreads();
    }
    if (t == 0) out[0] = (float)(red[0] / (double)redc[0]);
}

// ---------------- launcher ----------------
extern "C" void kernel_launch(void* const* d_in, const int* in_sizes, int n_in,
                              void* d_out, int out_size) {
    const float* logits = (const float*)d_in[0];
    const int*   gt     = (const int*)d_in[1];
    const int*   types  = (const int*)d_in[2];
    const void*  mask   = d_in[3];

    detect_mask_kernel<<<1, 256>>>((const unsigned char*)mask);
    group_build_kernel<<<NG, 32>>>(gt, types, mask);
    lse_kernel<<<BB*NN, 128>>>(logits, mask);
    gather_kernel<<<NG, 256>>>(logits);
    jv_kernel<<<NG, 32>>>();
    final_kernel<<<1, 256>>>((float*)d_out);
}

// round 2
// speedup vs baseline: 2.1105x; 2.1105x over previous
#include <cuda_runtime.h>
#include <cuda_bf16.h>
#include <math.h>

// Problem shape (fixed by the dataset)
#define BB 16
#define NN 1024
#define VV 4096
#define TT 8
#define NG (BB*TT)       // 128 (batch, type) groups
#define KMAX 128         // max group size (mean 64, sd ~7.8 -> +8.2 sigma headroom)
#define CPL 4            // columns per lane = KMAX/32

// ---------------- device scratch (static; no allocations) ----------------
__device__ int    d_mask_code;          // 0=uint8, 1=int32, 2=float32
__device__ int    d_cnt[NG];
__device__ int    d_idx[NG][KMAX];
__device__ int    d_tok[NG][KMAX];
__device__ float  d_cost[NG][KMAX*KMAX];
__device__ float  d_lse[BB*NN];
__device__ double d_val[NG];

// ---------------- helpers ----------------
__device__ __forceinline__ bool mask_at(const void* m, int code, int i) {
    if (code == 0) return ((const unsigned char*)m)[i] != 0;
    if (code == 1) return ((const int*)m)[i] != 0;
    return ((const float*)m)[i] != 0.0f;
}

// order-preserving float -> uint key (monotone), and inverse (exact bit ops)
__device__ __forceinline__ unsigned fkey(float f) {
    unsigned b = __float_as_uint(f);
    return (b & 0x80000000u) ? ~b : (b | 0x80000000u);
}
__device__ __forceinline__ float fkey_inv(unsigned k) {
    unsigned b = (k & 0x80000000u) ? (k ^ 0x80000000u) : ~k;
    return __uint_as_float(b);
}

// ---------------- kernel 1: classify mask dtype layout ----------------
__global__ void detect_mask_kernel(const unsigned char* m) {
    __shared__ int nz[4];
    if (threadIdx.x < 4) nz[threadIdx.x] = 0;
    __syncthreads();
    int local[4] = {0,0,0,0};
    for (int i = threadIdx.x; i < BB*NN; i += blockDim.x)
        if (m[i]) local[i & 3] = 1;
    for (int c = 0; c < 4; c++) if (local[c]) atomicOr(&nz[c], 1);
    __syncthreads();
    if (threadIdx.x == 0) {
        int code;
        if (nz[1])      code = 0;  // bytes at offset%4==1 nonzero -> uint8/bool layout
        else if (nz[0]) code = 1;  // only LSB of each word -> int32 0/1
        else            code = 2;  // pattern of 1.0f (bytes 2,3) -> float32
        d_mask_code = code;
    }
}

// ---------------- kernel 2: build (b,type) groups (ordered, deterministic) ---
__global__ void group_build_kernel(const int* __restrict__ gt,
                                   const int* __restrict__ types,
                                   const void* mask) {
    int g = blockIdx.x;
    int b = g / TT, t = g % TT;
    int lane = threadIdx.x;
    int code = d_mask_code;
    int base = b * NN;
    int cnt = 0;
    for (int p0 = 0; p0 < NN; p0 += 32) {
        int pos = p0 + lane;
        bool pred = (types[base + pos] == t) && mask_at(mask, code, base + pos);
        unsigned bal = __ballot_sync(0xFFFFFFFFu, pred);
        if (pred) {
            int r = cnt + __popc(bal & ((1u << lane) - 1u));
            if (r < KMAX) {
                d_idx[g][r] = pos;
                d_tok[g][r] = gt[base + pos];
            }
        }
        cnt += __popc(bal);
    }
    if (lane == 0) d_cnt[g] = min(cnt, KMAX);
}

// ---------------- kernel 3: per-masked-row logsumexp (memory-bound bulk) ----
__global__ void lse_kernel(const float* __restrict__ logits, const void* mask) {
    int r = blockIdx.x;                     // 0 .. BB*NN-1
    if (!mask_at(mask, d_mask_code, r)) {
        if (threadIdx.x == 0) d_lse[r] = 0.0f;
        return;
    }
    const float4* row = (const float4*)(logits + (size_t)r * VV);  // 1024 float4
    int t = threadIdx.x;                    // blockDim = 128
    float4 vb[8];
    float mx = -INFINITY;
    #pragma unroll
    for (int q = 0; q < 8; q++) {
        vb[q] = row[t + q * 128];
        mx = fmaxf(mx, fmaxf(fmaxf(vb[q].x, vb[q].y), fmaxf(vb[q].z, vb[q].w)));
    }
    __shared__ float sm[4];
    #pragma unroll
    for (int o = 16; o > 0; o >>= 1) mx = fmaxf(mx, __shfl_xor_sync(0xFFFFFFFFu, mx, o));
    if ((t & 31) == 0) sm[t >> 5] = mx;
    __syncthreads();
    mx = fmaxf(fmaxf(sm[0], sm[1]), fmaxf(sm[2], sm[3]));
    float s = 0.0f;
    #pragma unroll
    for (int q = 0; q < 8; q++)
        s += __expf(vb[q].x - mx) + __expf(vb[q].y - mx)
           + __expf(vb[q].z - mx) + __expf(vb[q].w - mx);
    __shared__ float ss[4];
    #pragma unroll
    for (int o = 16; o > 0; o >>= 1) s += __shfl_xor_sync(0xFFFFFFFFu, s, o);
    if ((t & 31) == 0) ss[t >> 5] = s;
    __syncthreads();
    if (t == 0) d_lse[r] = mx + logf(ss[0] + ss[1] + ss[2] + ss[3]);
}

// ---------------- kernel 4: gather cost matrices (cost = -logit) ------------
// 8 blocks per group to cover the latency of the scattered 4B gathers.
__global__ void gather_kernel(const float* __restrict__ logits) {
    int g = blockIdx.x;
    int k = d_cnt[g];
    if (k == 0) return;
    int b = g / TT;
    const float* base = logits + (size_t)b * NN * VV;
    int kk = k * k;
    int stride = blockDim.x * gridDim.y;
    for (int e = blockIdx.y * blockDim.x + threadIdx.x; e < kk; e += stride) {
        int i = e / k, j = e - i * k;
        d_cost[g][i * KMAX + j] = -__ldg(&base[(size_t)d_idx[g][i] * VV + d_tok[g][j]]);
    }
}

// ---------------- kernel 5: Jonker-Volgenant LSA, one warp per group --------
// Warm start: column reduction + greedy assignment (standard JV preprocessing,
// exact). Remaining free rows solved with shortest-augmenting-path Dijkstra in
// "absolute distance" form: per-step only relax + reduce; potential updates
// deferred to end of round. Cost matrix staged in shared memory.
extern __shared__ float cost_sh[];   // KMAX*KMAX floats = 64KB dynamic

__global__ void jv_kernel() {
    int g = blockIdx.x;
    int n = d_cnt[g];
    int lane = threadIdx.x;
    __shared__ float u_sh[KMAX + 1];
    __shared__ int   p_sh[KMAX + 1];
    __shared__ int   way_sh[KMAX + 1];
    __shared__ int   imin_sh[KMAX + 1];
    __shared__ int   x_sh[KMAX + 1];
    if (n == 0) { if (lane == 0) d_val[g] = 0.0; return; }

    // stage cost rows into shared (row stride KMAX, 16B aligned)
    {
        const float4* src = (const float4*)d_cost[g];
        float4* dst = (float4*)cost_sh;
        int nw = n * (KMAX / 4);
        for (int t = lane; t < nw; t += 32) dst[t] = src[t];
    }
    for (int t = lane; t <= n; t += 32) { u_sh[t] = 0.0f; p_sh[t] = 0; x_sh[t] = 0; }
    __syncwarp();

    // ---- column reduction: v[j] = min_i c[i][j], remember argmin row ----
    float v[CPL];
    int   im[CPL];
    #pragma unroll
    for (int q = 0; q < CPL; q++) { v[q] = INFINITY; im[q] = 0; }
    for (int i = 0; i < n; i++) {
        const float* row = cost_sh + i * KMAX;
        #pragma unroll
        for (int q = 0; q < CPL; q++) {
            int j = q * 32 + lane;
            if (j < n) {
                float c = row[j];
                if (c < v[q]) { v[q] = c; im[q] = i + 1; }
            }
        }
    }
    #pragma unroll
    for (int q = 0; q < CPL; q++) { int j = q * 32 + lane; if (j < n) imin_sh[j + 1] = im[q]; }
    __syncwarp();
    // greedy: assign each column to its argmin row if that row is still free
    if (lane == 0) {
        for (int j = 1; j <= n; j++) {
            int i = imin_sh[j];
            if (x_sh[i] == 0) { x_sh[i] = j; p_sh[j] = i; }
        }
    }
    __syncwarp();

    // ---- Dijkstra rounds for remaining free rows ----
    for (int i = 1; i <= n; i++) {
        if (x_sh[i] != 0) continue;            // preassigned by warm start
        if (lane == 0) p_sh[0] = i;
        float    dist[CPL];
        unsigned bkey[CPL];
        #pragma unroll
        for (int q = 0; q < CPL; q++) { dist[q] = INFINITY; bkey[q] = 0xFF800000u; }
        unsigned usedm = 0;
        __syncwarp();

        float D = 0.0f;        // absolute distance of last settled column
        int j0 = 0, i0 = i;
        while (true) {
            // mark previously chosen column as used (skip root j0==0)
            if (j0 > 0) {
                int ol = (j0 - 1) & 31, oq = (j0 - 1) >> 5;
                if (lane == ol) { usedm |= (1u << oq); bkey[oq] = 0xFFFFFFFFu; }
            }
            float ui0 = u_sh[i0];
            const float* crow = cost_sh + (size_t)(i0 - 1) * KMAX;
            float base = D - ui0;
            #pragma unroll
            for (int q = 0; q < CPL; q++) {
                int j = q * 32 + lane + 1;
                if (j <= n && !((usedm >> q) & 1u)) {
                    float cur = crow[j - 1] + (base - v[q]);
                    if (cur < dist[q]) { dist[q] = cur; bkey[q] = fkey(cur); way_sh[j] = j0; }
                }
            }
            // per-lane best over cached keys, then warp min + argmin
            unsigned bk = bkey[0]; int bq = 0;
            #pragma unroll
            for (int q = 1; q < CPL; q++) if (bkey[q] < bk) { bk = bkey[q]; bq = q; }
            unsigned kmin = __reduce_min_sync(0xFFFFFFFFu, bk);
            int jc = (bk == kmin) ? (bq * 32 + lane + 1) : 0x7FFFFFFF;
            int j1 = (int)__reduce_min_sync(0xFFFFFFFFu, (unsigned)jc);
            D = fkey_inv(kmin);

            j0 = j1;
            i0 = p_sh[j0];
            if (i0 == 0) break;                // reached a free column
        }

        // end-of-round potential updates: incr_j = D_final - dist[j] for used j
        if (lane == 0) u_sh[i] += D;           // root row
        #pragma unroll
        for (int q = 0; q < CPL; q++) {
            if ((usedm >> q) & 1u) {
                int j = q * 32 + lane + 1;
                float incr = D - dist[q];
                v[q] -= incr;
                u_sh[p_sh[j]] += incr;         // distinct rows -> no conflict
            }
        }
        __syncwarp();
        // augment along the alternating path
        if (lane == 0) {
            int j = j0;
            while (j) { int jp = way_sh[j]; p_sh[j] = p_sh[jp]; j = jp; }
        }
        __syncwarp();
    }

    // optimal value = sum_j cost[p[j]-1][j-1]
    double s = 0.0;
    for (int j = lane + 1; j <= n; j += 32) {
        int pi = p_sh[j];
        s += (double)cost_sh[(size_t)(pi - 1) * KMAX + (j - 1)];
    }
    #pragma unroll
    for (int o = 16; o > 0; o >>= 1) s += __shfl_down_sync(0xFFFFFFFFu, s, o);
    if (lane == 0) d_val[g] = s;
}

// ---------------- kernel 6: deterministic final reduction -------------------
__global__ void final_kernel(float* out) {
    __shared__ double red[256];
    __shared__ int    redc[256];
    int t = threadIdx.x;
    double s = 0.0;
    for (int i = t; i < BB*NN; i += 256) s += (double)d_lse[i];
    int cnt = 0;
    if (t < NG) { s += d_val[t]; cnt = d_cnt[t]; }
    red[t] = s; redc[t] = cnt;
    __syncthreads();
    for (int o = 128; o > 0; o >>= 1) {
        if (t < o) { red[t] += red[t + o]; redc[t] += redc[t + o]; }
        __syncthreads();
    }
    if (t == 0) out[0] = (float)(red[0] / (double)redc[0]);
}

// ---------------- launcher ----------------
extern "C" void kernel_launch(void* const* d_in, const int* in_sizes, int n_in,
                              void* d_out, int out_size) {
    const float* logits = (const float*)d_in[0];
    const int*   gt     = (const int*)d_in[1];
    const int*   types  = (const int*)d_in[2];
    const void*  mask   = d_in[3];

    cudaFuncSetAttribute(jv_kernel, cudaFuncAttributeMaxDynamicSharedMemorySize,
                         KMAX * KMAX * (int)sizeof(float));

    detect_mask_kernel<<<1, 256>>>((const unsigned char*)mask);
    group_build_kernel<<<NG, 32>>>(gt, types, mask);
    lse_kernel<<<BB*NN, 128>>>(logits, mask);
    gather_kernel<<<dim3(NG, 8), 256>>>(logits);
    jv_kernel<<<NG, 32, KMAX * KMAX * (int)sizeof(float)>>>();
    final_kernel<<<1, 256>>>((float*)d_out);
}